// round 2
// baseline (speedup 1.0000x reference)
#include <cuda_runtime.h>
#include <stdint.h>
#include <math.h>

// ---- JAX RNG mode: modern JAX defaults jax_threefry_partitionable=True.
// If rel_err comes back ~O(1), flip to 0 (legacy split / pair-indexed bits).
#define PARTITIONABLE 1

constexpr int Bn   = 4;
constexpr int Tn   = 480000;
constexpr int DIMn = 9;               // HARMONIC_NUM + 1
constexpr int CHUNK = 1024;
constexpr int TPB   = 128;
constexpr int SPT   = CHUNK / TPB;    // 8
constexpr int NCH   = (Tn + CHUNK - 1) / CHUNK;  // 469

constexpr float LO_NORMAL = -0.99999994f;            // nextafter(-1,0) fp32
constexpr float SQRT2F    = 1.41421356237309504880f; // 0x3FB504F3
constexpr float TWO_PI_F  = 6.28318530717958647692f; // 0x40C90FDB

struct RandIni { float v[Bn * DIMn]; };
struct NKey    { uint32_t k0, k1; };

// per-(b,h) per-chunk fp64 sums; K2 converts in place to exclusive prefixes
__device__ double g_csum[Bn * DIMn * NCH];

// ---------------- threefry2x32-20 (JAX-compatible) ----------------
__host__ __device__ __forceinline__ uint32_t rotl32(uint32_t x, int r) {
#ifdef __CUDA_ARCH__
  return __funnelshift_l(x, x, r);
#else
  return (x << r) | (x >> (32 - r));
#endif
}

__host__ __device__ __forceinline__ void tf2x32(uint32_t k0, uint32_t k1,
                                                uint32_t x0, uint32_t x1,
                                                uint32_t& o0, uint32_t& o1) {
  uint32_t k2 = k0 ^ k1 ^ 0x1BD11BDAu;
#define TFR(r) { x0 += x1; x1 = rotl32(x1, (r)); x1 ^= x0; }
  x0 += k0; x1 += k1;
  TFR(13) TFR(15) TFR(26) TFR(6)
  x0 += k1; x1 += k2 + 1u;
  TFR(17) TFR(29) TFR(16) TFR(24)
  x0 += k2; x1 += k0 + 2u;
  TFR(13) TFR(15) TFR(26) TFR(6)
  x0 += k0; x1 += k1 + 3u;
  TFR(17) TFR(29) TFR(16) TFR(24)
  x0 += k1; x1 += k2 + 4u;
  TFR(13) TFR(15) TFR(26) TFR(6)
  x0 += k2; x1 += k0 + 5u;
#undef TFR
  o0 = x0; o1 = x1;
}

// random bits for a flat array of `total` 32-bit draws, element `idx`
__host__ __device__ __forceinline__ uint32_t rng_bits(uint32_t k0, uint32_t k1,
                                                      uint32_t total, uint32_t idx) {
  uint32_t a, b;
#if PARTITIONABLE
  (void)total;
  tf2x32(k0, k1, 0u, idx, a, b);
  return a ^ b;
#else
  uint32_t half = total >> 1;
  if (idx < half) { tf2x32(k0, k1, idx, idx + half, a, b); return a; }
  else            { tf2x32(k0, k1, idx - half, idx, a, b); return b; }
#endif
}

__host__ __device__ __forceinline__ float bits01(uint32_t bits) {
  union { uint32_t u; float f; } c;
  c.u = (bits >> 9) | 0x3F800000u;
  return c.f - 1.0f;
}

// ---------------- XLA ErfInv32 (Giles) ----------------
__device__ __forceinline__ float erfinv_xla(float x) {
  float w = -log1pf(-x * x);
  float p;
  if (w < 5.0f) {
    w = w - 2.5f;
    p =             2.81022636e-08f;
    p = fmaf(p, w,  3.43273939e-07f);
    p = fmaf(p, w, -3.5233877e-06f);
    p = fmaf(p, w, -4.39150654e-06f);
    p = fmaf(p, w,  0.00021858087f);
    p = fmaf(p, w, -0.00125372503f);
    p = fmaf(p, w, -0.00417768164f);
    p = fmaf(p, w,  0.246640727f);
    p = fmaf(p, w,  1.50140941f);
  } else {
    w = sqrtf(w) - 3.0f;
    p =            -0.000200214257f;
    p = fmaf(p, w,  0.000100950558f);
    p = fmaf(p, w,  0.00134934322f);
    p = fmaf(p, w, -0.00367342844f);
    p = fmaf(p, w,  0.00573950773f);
    p = fmaf(p, w, -0.0076224613f);
    p = fmaf(p, w,  0.00943887047f);
    p = fmaf(p, w,  1.00167406f);
    p = fmaf(p, w,  2.83297682f);
  }
  return p * x;
}

// rad value exactly as the reference computes it (fp32 mul, IEEE fp32 div)
__device__ __forceinline__ float rad_val(float f0v, int h) {
  return __fdiv_rn(f0v * (float)(h + 1), 48000.0f);
}

// ---------------- K1: per-chunk fp64 sums ----------------
__global__ void __launch_bounds__(TPB) k_chunksum(const float* __restrict__ f0, RandIni ri) {
  int b = blockIdx.y, c = blockIdx.x;
  int base = c * CHUNK;
  int n = min(CHUNK, Tn - base);
  int tid = threadIdx.x;

  double acc[DIMn];
#pragma unroll
  for (int h = 0; h < DIMn; h++) acc[h] = 0.0;

  int s0 = tid * SPT;
  if (s0 < n) {
    const float4* p = reinterpret_cast<const float4*>(f0 + (size_t)b * Tn + base + s0);
    float4 a = p[0], bb = p[1];
    float fv[8] = {a.x, a.y, a.z, a.w, bb.x, bb.y, bb.z, bb.w};
#pragma unroll
    for (int j = 0; j < 8; j++) {
      float v = fv[j];
      bool first = (base + s0 + j) == 0;
#pragma unroll
      for (int h = 0; h < DIMn; h++) {
        float rad = rad_val(v, h);
        if (first) rad += ri.v[b * DIMn + h];
        acc[h] += (double)rad;
      }
    }
  }

  // block reduce (warp shfl + shared)
#pragma unroll
  for (int h = 0; h < DIMn; h++) {
    double x = acc[h];
#pragma unroll
    for (int o = 16; o > 0; o >>= 1) x += __shfl_down_sync(0xffffffffu, x, o);
    acc[h] = x;
  }
  __shared__ double sm[TPB / 32][DIMn];
  int warp = tid >> 5, lane = tid & 31;
  if (lane == 0)
#pragma unroll
    for (int h = 0; h < DIMn; h++) sm[warp][h] = acc[h];
  __syncthreads();
  if (tid == 0) {
#pragma unroll
    for (int h = 0; h < DIMn; h++) {
      double s = sm[0][h] + sm[1][h] + sm[2][h] + sm[3][h];
      g_csum[(b * DIMn + h) * NCH + c] = s;
    }
  }
}

// ---------------- K2: exclusive scan of chunk sums (36 series) ----------------
__global__ void k_scan() {
  int s = blockIdx.x;                 // 0..B*DIM-1
  int lane = threadIdx.x;             // 32 threads
  constexpr int PER = (NCH + 31) / 32;  // 15
  double* row = &g_csum[s * NCH];

  double v[PER];
  double tot = 0.0;
  int st = lane * PER;
#pragma unroll
  for (int j = 0; j < PER; j++) {
    int c = st + j;
    v[j] = (c < NCH) ? row[c] : 0.0;
    tot += v[j];
  }
  // exclusive scan of lane totals
  double x = tot;
#pragma unroll
  for (int o = 1; o < 32; o <<= 1) {
    double y = __shfl_up_sync(0xffffffffu, x, o);
    if (lane >= o) x += y;
  }
  double run = x - tot;
#pragma unroll
  for (int j = 0; j < PER; j++) {
    int c = st + j;
    if (c < NCH) {
      double old = v[j];
      row[c] = run;        // exclusive prefix, in place
      run += old;
    }
  }
}

// ---------------- K3: main (phase + sine + noise) ----------------
__global__ void __launch_bounds__(TPB) k_main(const float* __restrict__ f0,
                                              float* __restrict__ out,
                                              RandIni ri, NKey nk) {
  constexpr uint32_t TOTAL = (uint32_t)Bn * (uint32_t)Tn * (uint32_t)DIMn;
  int b = blockIdx.y, c = blockIdx.x;
  int base = c * CHUNK;
  int n = min(CHUNK, Tn - base);      // 1024 or 768, multiple of TPB
  int tid = threadIdx.x;
  int warp = tid >> 5, lane = tid & 31;
  int s0 = tid * SPT;
  bool act = s0 < n;

  __shared__ float so[TPB * 73];      // padded staging: thread t owns [t*73, t*73+72)
  __shared__ double wsum[TPB / 32][DIMn];

  float fv[8];
  if (act) {
    const float4* p = reinterpret_cast<const float4*>(f0 + (size_t)b * Tn + base + s0);
    float4 a = p[0], bb = p[1];
    fv[0]=a.x; fv[1]=a.y; fv[2]=a.z; fv[3]=a.w;
    fv[4]=bb.x; fv[5]=bb.y; fv[6]=bb.z; fv[7]=bb.w;
  }

  // pass 1: thread-local fp64 sums over its 8 samples
  double acc[DIMn];
#pragma unroll
  for (int h = 0; h < DIMn; h++) acc[h] = 0.0;
  if (act) {
#pragma unroll
    for (int j = 0; j < 8; j++) {
      float v = fv[j];
      bool first = (base + s0 + j) == 0;
#pragma unroll
      for (int h = 0; h < DIMn; h++) {
        float rad = rad_val(v, h);
        if (first) rad += ri.v[b * DIMn + h];
        acc[h] += (double)rad;
      }
    }
  }

  // warp-inclusive scan per harmonic
  double incl[DIMn];
#pragma unroll
  for (int h = 0; h < DIMn; h++) {
    double x = acc[h];
#pragma unroll
    for (int o = 1; o < 32; o <<= 1) {
      double y = __shfl_up_sync(0xffffffffu, x, o);
      if (lane >= o) x += y;
    }
    incl[h] = x;
  }
  if (lane == 31)
#pragma unroll
    for (int h = 0; h < DIMn; h++) wsum[warp][h] = incl[h];
  __syncthreads();

  // running fractional phase per harmonic (exclusive prefix, frac'd)
  double run[DIMn];
#pragma unroll
  for (int h = 0; h < DIMn; h++) {
    double wex = 0.0;
#pragma unroll
    for (int w = 0; w < TPB / 32; w++)
      if (w < warp) wex += wsum[w][h];
    double start = g_csum[(b * DIMn + h) * NCH + c] + wex + (incl[h] - acc[h]);
    run[h] = start - floor(start);
  }

  if (act) {
#pragma unroll
    for (int j = 0; j < 8; j++) {
      float v = fv[j];
      int t = base + s0 + j;
      bool first = (t == 0);
      uint32_t idxbase = ((uint32_t)(b * Tn + t)) * (uint32_t)DIMn;
      float uv  = (v > 0.0f) ? 1.0f : 0.0f;
      float amp = uv * 0.003f + (1.0f - uv) * (0.1f / 3.0f);
      int slot = tid * 73 + j * DIMn;
#pragma unroll
      for (int h = 0; h < DIMn; h++) {
        float rad = rad_val(v, h);
        if (first) rad += ri.v[b * DIMn + h];
        run[h] += (double)rad;
        run[h] -= floor(run[h]);
        float ph = (float)run[h];
        float sw = __sinf(TWO_PI_F * ph) * 0.1f;

        uint32_t bits = rng_bits(nk.k0, nk.k1, TOTAL, idxbase + (uint32_t)h);
        float u = fmaxf(LO_NORMAL, bits01(bits) * 2.0f + LO_NORMAL);
        float nr = SQRT2F * erfinv_xla(u);

        so[slot + h] = sw * uv + amp * nr;
      }
    }
  }

  __syncthreads();
  // coalesced writeout: logical word w -> sample i=w/72-per-thread mapping
  int words = n * DIMn;
  size_t outbase = ((size_t)b * Tn + (size_t)base) * (size_t)DIMn;
  for (int w = tid; w < words; w += TPB) {
    int th = w / 72;        // owning thread (72 = 8 samples * 9 harmonics)
    int of = w - th * 72;
    out[outbase + (size_t)w] = so[th * 73 + of];
  }
}

// ---------------- host ----------------
extern "C" void kernel_launch(void* const* d_in, const int* in_sizes, int n_in,
                              void* d_out, int out_size) {
  (void)in_sizes; (void)n_in; (void)out_size;
  const float* f0 = (const float*)d_in[0];
  float* out = (float*)d_out;

  // derive keys: k_ini, k_noise = split(key(42)); key(42) = (0, 42)
  uint32_t ik0, ik1, nk0, nk1;
#if PARTITIONABLE
  { uint32_t a, b;
    tf2x32(0u, 42u, 0u, 0u, a, b); ik0 = a; ik1 = b;
    tf2x32(0u, 42u, 0u, 1u, a, b); nk0 = a; nk1 = b; }
#else
  { uint32_t a0, b0, a1, b1;
    tf2x32(0u, 42u, 0u, 2u, a0, b0);
    tf2x32(0u, 42u, 1u, 3u, a1, b1);
    ik0 = a0; ik1 = a1;   // key0 = (out0(0,2), out0(1,3))
    nk0 = b0; nk1 = b1; } // key1 = (out1(0,2), out1(1,3))
#endif

  // rand_ini = uniform(k_ini, (B, DIM)); column 0 zeroed
  RandIni ri;
  for (uint32_t i = 0; i < (uint32_t)(Bn * DIMn); i++) {
    uint32_t bits = rng_bits(ik0, ik1, (uint32_t)(Bn * DIMn), i);
    float u = bits01(bits);
    ri.v[i] = u < 0.0f ? 0.0f : u;  // lax.max(0, u)
  }
  for (int b = 0; b < Bn; b++) ri.v[b * DIMn] = 0.0f;

  NKey nk{nk0, nk1};

  dim3 grid(NCH, Bn);
  k_chunksum<<<grid, TPB>>>(f0, ri);
  k_scan<<<Bn * DIMn, 32>>>();
  k_main<<<grid, TPB>>>(f0, out, ri, nk);
}

// round 3
// speedup vs baseline: 2.3606x; 2.3606x over previous
#include <cuda_runtime.h>
#include <stdint.h>
#include <math.h>

#define PARTITIONABLE 1

constexpr int Bn   = 4;
constexpr int Tn   = 480000;
constexpr int DIMn = 9;
constexpr int CHUNK = 1024;
constexpr int TPB   = 128;
constexpr int SPT   = CHUNK / TPB;               // 8
constexpr int NCH   = (Tn + CHUNK - 1) / CHUNK;  // 469

constexpr float LO_NORMAL = -0.99999994f;
constexpr float SQRT2F    = 1.41421356237309504880f;
constexpr float RCP48K    = 2.08333333333333333e-05f;  // fl(1/48000)

struct RandIniFx { unsigned long long v[Bn * DIMn]; };
struct NKey      { uint32_t k0, k1; };

// per-(b,h) per-chunk u64 fixed-point sums (2^-33 turns); K2 -> exclusive prefixes
__device__ unsigned long long g_csum[Bn * DIMn * NCH];

// ---------------- threefry2x32-20 ----------------
__host__ __device__ __forceinline__ uint32_t rotl32(uint32_t x, int r) {
#ifdef __CUDA_ARCH__
  return __funnelshift_l(x, x, r);
#else
  return (x << r) | (x >> (32 - r));
#endif
}

__host__ __device__ __forceinline__ void tf2x32(uint32_t k0, uint32_t k1,
                                                uint32_t x0, uint32_t x1,
                                                uint32_t& o0, uint32_t& o1) {
  uint32_t k2 = k0 ^ k1 ^ 0x1BD11BDAu;
#define TFR(r) { x0 += x1; x1 = rotl32(x1, (r)); x1 ^= x0; }
  x0 += k0; x1 += k1;
  TFR(13) TFR(15) TFR(26) TFR(6)
  x0 += k1; x1 += k2 + 1u;
  TFR(17) TFR(29) TFR(16) TFR(24)
  x0 += k2; x1 += k0 + 2u;
  TFR(13) TFR(15) TFR(26) TFR(6)
  x0 += k0; x1 += k1 + 3u;
  TFR(17) TFR(29) TFR(16) TFR(24)
  x0 += k1; x1 += k2 + 4u;
  TFR(13) TFR(15) TFR(26) TFR(6)
  x0 += k2; x1 += k0 + 5u;
#undef TFR
  o0 = x0; o1 = x1;
}

__host__ __device__ __forceinline__ uint32_t rng_bits(uint32_t k0, uint32_t k1,
                                                      uint32_t idx) {
  uint32_t a, b;
  tf2x32(k0, k1, 0u, idx, a, b);
  return a ^ b;
}

__host__ __device__ __forceinline__ float bits01(uint32_t bits) {
  union { uint32_t u; float f; } c;
  c.u = (bits >> 9) | 0x3F800000u;
  return c.f - 1.0f;
}

// ---------------- XLA ErfInv32 with fast log ----------------
__device__ __forceinline__ float erfinv_xla(float x) {
  // reference: w = -log1p(-x*x). 1 - fl(x^2) is Sterbenz-exact where it matters;
  // Delta-w budget here is ~1e-2 (noise slack), __logf err 2^-21.
  float w = -__logf(fmaf(-x, x, 1.0f));
  float p;
  if (w < 5.0f) {
    w = w - 2.5f;
    p =             2.81022636e-08f;
    p = fmaf(p, w,  3.43273939e-07f);
    p = fmaf(p, w, -3.5233877e-06f);
    p = fmaf(p, w, -4.39150654e-06f);
    p = fmaf(p, w,  0.00021858087f);
    p = fmaf(p, w, -0.00125372503f);
    p = fmaf(p, w, -0.00417768164f);
    p = fmaf(p, w,  0.246640727f);
    p = fmaf(p, w,  1.50140941f);
  } else {
    w = sqrtf(w) - 3.0f;
    p =            -0.000200214257f;
    p = fmaf(p, w,  0.000100950558f);
    p = fmaf(p, w,  0.00134934322f);
    p = fmaf(p, w, -0.00367342844f);
    p = fmaf(p, w,  0.00573950773f);
    p = fmaf(p, w, -0.0076224613f);
    p = fmaf(p, w,  0.00943887047f);
    p = fmaf(p, w,  1.00167406f);
    p = fmaf(p, w,  2.83297682f);
  }
  return p * x;
}

// correctly-rounded x/48000 via Markstein (bit-identical to __fdiv_rn, no MUFU)
__device__ __forceinline__ float div48k(float x) {
  float q0 = __fmul_rn(x, RCP48K);
  float e  = fmaf(-48000.0f, q0, x);
  return fmaf(e, RCP48K, q0);
}

// rad in u32 fixed point (2^-33 turns) — exact
__device__ __forceinline__ uint32_t rad_fx(float f0v, int h) {
  float rad = div48k(__fmul_rn(f0v, (float)(h + 1)));
  return (uint32_t)(rad * 8589934592.0f);   // rad * 2^33, exact integer value
}

// sin(2*pi*frac) * 0.1 from u32 phase (turns). No MUFU.
__device__ __forceinline__ float sine_from_p32(uint32_t p32) {
  bool refl = (int32_t)(p32 + 0x40000000u) < 0;
  int32_t yi = refl ? (int32_t)(0x80000000u - p32) : (int32_t)p32;
  float x  = (float)yi * 4.65661287307739258e-10f;   // 2^-31 -> x in [-0.5,0.5]
  float x2 = x * x;
  float p =            0.0821458866f;     // sin(pi x) odd Taylor, deg 9
  p = fmaf(p, x2, -0.599264529f);
  p = fmaf(p, x2,  2.55016404f);
  p = fmaf(p, x2, -5.16771278f);
  p = fmaf(p, x2,  3.14159265f);
  return (x * 0.1f) * p;
}

// ---------------- K1: per-chunk u64 sums ----------------
__global__ void __launch_bounds__(TPB) k_chunksum(const float* __restrict__ f0, RandIniFx ri) {
  int b = blockIdx.y, c = blockIdx.x;
  int base = c * CHUNK;
  int n = min(CHUNK, Tn - base);
  int tid = threadIdx.x;

  unsigned long long acc[DIMn];
#pragma unroll
  for (int h = 0; h < DIMn; h++) acc[h] = 0ull;

  int s0 = tid * SPT;
  if (s0 < n) {
    const float4* p = reinterpret_cast<const float4*>(f0 + (size_t)b * Tn + base + s0);
    float4 a = p[0], bb = p[1];
    float fv[8] = {a.x, a.y, a.z, a.w, bb.x, bb.y, bb.z, bb.w};
#pragma unroll
    for (int j = 0; j < 8; j++) {
      bool first = (base + s0 + j) == 0;
#pragma unroll
      for (int h = 0; h < DIMn; h++) {
        unsigned long long r = (unsigned long long)rad_fx(fv[j], h);
        if (first) r += ri.v[b * DIMn + h];
        acc[h] += r;
      }
    }
  }

#pragma unroll
  for (int h = 0; h < DIMn; h++) {
    unsigned long long x = acc[h];
#pragma unroll
    for (int o = 16; o > 0; o >>= 1) x += __shfl_down_sync(0xffffffffu, x, o);
    acc[h] = x;
  }
  __shared__ unsigned long long sm[TPB / 32][DIMn];
  int warp = tid >> 5, lane = tid & 31;
  if (lane == 0)
#pragma unroll
    for (int h = 0; h < DIMn; h++) sm[warp][h] = acc[h];
  __syncthreads();
  if (tid == 0) {
#pragma unroll
    for (int h = 0; h < DIMn; h++)
      g_csum[(b * DIMn + h) * NCH + c] = sm[0][h] + sm[1][h] + sm[2][h] + sm[3][h];
  }
}

// ---------------- K2: exclusive scan of chunk sums ----------------
__global__ void k_scan() {
  int s = blockIdx.x;
  int lane = threadIdx.x;
  constexpr int PER = (NCH + 31) / 32;   // 15
  unsigned long long* row = &g_csum[(size_t)s * NCH];

  unsigned long long v[PER];
  unsigned long long tot = 0ull;
  int st = lane * PER;
#pragma unroll
  for (int j = 0; j < PER; j++) {
    int c = st + j;
    v[j] = (c < NCH) ? row[c] : 0ull;
    tot += v[j];
  }
  unsigned long long x = tot;
#pragma unroll
  for (int o = 1; o < 32; o <<= 1) {
    unsigned long long y = __shfl_up_sync(0xffffffffu, x, o);
    if (lane >= o) x += y;
  }
  unsigned long long run = x - tot;
#pragma unroll
  for (int j = 0; j < PER; j++) {
    int c = st + j;
    if (c < NCH) {
      unsigned long long old = v[j];
      row[c] = run;
      run += old;
    }
  }
}

// ---------------- K3: main ----------------
__global__ void __launch_bounds__(TPB) k_main(const float* __restrict__ f0,
                                              float* __restrict__ out,
                                              RandIniFx ri, NKey nk) {
  int b = blockIdx.y, c = blockIdx.x;
  int base = c * CHUNK;
  int n = min(CHUNK, Tn - base);
  int tid = threadIdx.x;
  int warp = tid >> 5, lane = tid & 31;
  int s0 = tid * SPT;
  bool act = s0 < n;

  __shared__ float so[TPB * 73];
  __shared__ unsigned long long wsum[TPB / 32][DIMn];

  float fv[8];
  uint32_t rfx[8][DIMn];
  if (act) {
    const float4* p = reinterpret_cast<const float4*>(f0 + (size_t)b * Tn + base + s0);
    float4 a = p[0], bb = p[1];
    fv[0]=a.x; fv[1]=a.y; fv[2]=a.z; fv[3]=a.w;
    fv[4]=bb.x; fv[5]=bb.y; fv[6]=bb.z; fv[7]=bb.w;
  }

  // thread-local u64 sums over 8 samples (rads cached for reuse)
  unsigned long long acc[DIMn];
#pragma unroll
  for (int h = 0; h < DIMn; h++) acc[h] = 0ull;
  if (act) {
#pragma unroll
    for (int j = 0; j < 8; j++) {
#pragma unroll
      for (int h = 0; h < DIMn; h++) {
        uint32_t r = rad_fx(fv[j], h);
        rfx[j][h] = r;
        unsigned long long rr = r;
        if ((base + s0 + j) == 0) rr += ri.v[b * DIMn + h];
        acc[h] += rr;
      }
    }
  }

  // warp-inclusive scan per harmonic
  unsigned long long incl[DIMn];
#pragma unroll
  for (int h = 0; h < DIMn; h++) {
    unsigned long long x = acc[h];
#pragma unroll
    for (int o = 1; o < 32; o <<= 1) {
      unsigned long long y = __shfl_up_sync(0xffffffffu, x, o);
      if (lane >= o) x += y;
    }
    incl[h] = x;
  }
  if (lane == 31)
#pragma unroll
    for (int h = 0; h < DIMn; h++) wsum[warp][h] = incl[h];
  __syncthreads();

  unsigned long long run[DIMn];
#pragma unroll
  for (int h = 0; h < DIMn; h++) {
    unsigned long long wex = 0ull;
#pragma unroll
    for (int w = 0; w < TPB / 32; w++)
      if (w < warp) wex += wsum[w][h];
    run[h] = g_csum[(b * DIMn + h) * NCH + c] + wex + (incl[h] - acc[h]);
  }

  if (act) {
#pragma unroll
    for (int j = 0; j < 8; j++) {
      float v = fv[j];
      int t = base + s0 + j;
      uint32_t idxbase = ((uint32_t)(b * Tn + t)) * (uint32_t)DIMn;
      float uv  = (v > 0.0f) ? 1.0f : 0.0f;
      float amp = uv * 0.003f + (1.0f - uv) * (0.1f / 3.0f);
      int slot = tid * 73 + j * DIMn;
#pragma unroll
      for (int h = 0; h < DIMn; h++) {
        unsigned long long rr = rfx[j][h];
        if (t == 0) rr += ri.v[b * DIMn + h];
        run[h] += rr;
        uint32_t p32 = (uint32_t)(run[h] >> 1);     // frac bits [32:1]
        float sw = sine_from_p32(p32);              // sin(2*pi*frac)*0.1

        uint32_t bits = rng_bits(nk.k0, nk.k1, idxbase + (uint32_t)h);
        float u = fmaxf(LO_NORMAL, fmaf(bits01(bits), 2.0f, LO_NORMAL));
        float nr = SQRT2F * erfinv_xla(u);

        so[slot + h] = sw * uv + amp * nr;
      }
    }
  }

  __syncthreads();
  int words = n * DIMn;
  size_t outbase = ((size_t)b * Tn + (size_t)base) * (size_t)DIMn;
  for (int w = tid; w < words; w += TPB) {
    int th = w / 72;
    int of = w - th * 72;
    out[outbase + (size_t)w] = so[th * 73 + of];
  }
}

// ---------------- host ----------------
extern "C" void kernel_launch(void* const* d_in, const int* in_sizes, int n_in,
                              void* d_out, int out_size) {
  (void)in_sizes; (void)n_in; (void)out_size;
  const float* f0 = (const float*)d_in[0];
  float* out = (float*)d_out;

  uint32_t ik0, ik1, nk0, nk1;
  { uint32_t a, b;
    tf2x32(0u, 42u, 0u, 0u, a, b); ik0 = a; ik1 = b;
    tf2x32(0u, 42u, 0u, 1u, a, b); nk0 = a; nk1 = b; }

  RandIniFx ri;
  for (uint32_t i = 0; i < (uint32_t)(Bn * DIMn); i++) {
    uint32_t bits = rng_bits(ik0, ik1, i);
    float u = bits01(bits);
    if (u < 0.0f) u = 0.0f;
    ri.v[i] = (unsigned long long)((double)u * 8589934592.0);  // exact: u mult of 2^-23
  }
  for (int b = 0; b < Bn; b++) ri.v[b * DIMn] = 0ull;

  NKey nk{nk0, nk1};

  dim3 grid(NCH, Bn);
  k_chunksum<<<grid, TPB>>>(f0, ri);
  k_scan<<<Bn * DIMn, 32>>>();
  k_main<<<grid, TPB>>>(f0, out, ri, nk);
}

// round 4
// speedup vs baseline: 3.1403x; 1.3303x over previous
#include <cuda_runtime.h>
#include <stdint.h>
#include <math.h>

constexpr int Bn   = 4;
constexpr int Tn   = 480000;
constexpr int DIMn = 9;
constexpr int CHUNK = 1024;
constexpr int TPB   = 128;
constexpr int SPT   = CHUNK / TPB;               // 8
constexpr int NCH   = (Tn + CHUNK - 1) / CHUNK;  // 469

constexpr float LO_NORMAL = -0.99999994f;
constexpr float SQRT2F    = 1.41421356237309504880f;
constexpr float RCP48K    = 2.08333333333333333e-05f;  // fl(1/48000)

struct RandIniFx { unsigned long long v[Bn * DIMn]; };
struct NKey      { uint32_t k0, k1; };

// per-(b,h) per-chunk u64 fixed-point sums (2^-33 turns); K2 -> exclusive prefixes
__device__ unsigned long long g_csum[Bn * DIMn * NCH];

// ---------------- threefry2x32-20 ----------------
__host__ __device__ __forceinline__ uint32_t rotl32(uint32_t x, int r) {
#ifdef __CUDA_ARCH__
  return __funnelshift_l(x, x, r);
#else
  return (x << r) | (x >> (32 - r));
#endif
}

__host__ __device__ __forceinline__ void tf2x32(uint32_t k0, uint32_t k1,
                                                uint32_t x0, uint32_t x1,
                                                uint32_t& o0, uint32_t& o1) {
  uint32_t k2 = k0 ^ k1 ^ 0x1BD11BDAu;
#define TFR(r) { x0 += x1; x1 = rotl32(x1, (r)); x1 ^= x0; }
  x0 += k0; x1 += k1;
  TFR(13) TFR(15) TFR(26) TFR(6)
  x0 += k1; x1 += k2 + 1u;
  TFR(17) TFR(29) TFR(16) TFR(24)
  x0 += k2; x1 += k0 + 2u;
  TFR(13) TFR(15) TFR(26) TFR(6)
  x0 += k0; x1 += k1 + 3u;
  TFR(17) TFR(29) TFR(16) TFR(24)
  x0 += k1; x1 += k2 + 4u;
  TFR(13) TFR(15) TFR(26) TFR(6)
  x0 += k2; x1 += k0 + 5u;
#undef TFR
  o0 = x0; o1 = x1;
}

__host__ __device__ __forceinline__ uint32_t rng_bits(uint32_t k0, uint32_t k1,
                                                      uint32_t idx) {
  uint32_t a, b;
  tf2x32(k0, k1, 0u, idx, a, b);
  return a ^ b;
}

__host__ __device__ __forceinline__ float bits01(uint32_t bits) {
  union { uint32_t u; float f; } c;
  c.u = (bits >> 9) | 0x3F800000u;
  return c.f - 1.0f;
}

// ---------------- XLA ErfInv32 (fast log; noise error budget ~1e-2) --------
__device__ __forceinline__ float erfinv_xla(float x) {
  float w = -__logf(fmaf(-x, x, 1.0f));
  float p;
  if (w < 5.0f) {
    w = w - 2.5f;
    p =             2.81022636e-08f;
    p = fmaf(p, w,  3.43273939e-07f);
    p = fmaf(p, w, -3.5233877e-06f);
    p = fmaf(p, w, -4.39150654e-06f);
    p = fmaf(p, w,  0.00021858087f);
    p = fmaf(p, w, -0.00125372503f);
    p = fmaf(p, w, -0.00417768164f);
    p = fmaf(p, w,  0.246640727f);
    p = fmaf(p, w,  1.50140941f);
  } else {
    w = sqrtf(w) - 3.0f;
    p =            -0.000200214257f;
    p = fmaf(p, w,  0.000100950558f);
    p = fmaf(p, w,  0.00134934322f);
    p = fmaf(p, w, -0.00367342844f);
    p = fmaf(p, w,  0.00573950773f);
    p = fmaf(p, w, -0.0076224613f);
    p = fmaf(p, w,  0.00943887047f);
    p = fmaf(p, w,  1.00167406f);
    p = fmaf(p, w,  2.83297682f);
  }
  return p * x;
}

// correctly-rounded x/48000 via Markstein (bit-identical to __fdiv_rn)
__device__ __forceinline__ float div48k(float x) {
  float q0 = __fmul_rn(x, RCP48K);
  float e  = fmaf(-48000.0f, q0, x);
  return fmaf(e, RCP48K, q0);
}

// rad in u32 fixed point (2^-33 turns) — exact
__device__ __forceinline__ uint32_t rad_fx(float f0v, int h) {
  float rad = div48k(__fmul_rn(f0v, (float)(h + 1)));
  return (uint32_t)(rad * 8589934592.0f);   // rad * 2^33
}

// sin(2*pi*frac) * 0.1 from u32 phase (2^-32 turns). No MUFU.
__device__ __forceinline__ float sine_from_p32(uint32_t p32) {
  bool refl = (int32_t)(p32 + 0x40000000u) < 0;
  int32_t yi = refl ? (int32_t)(0x80000000u - p32) : (int32_t)p32;
  float x  = (float)yi * 4.65661287307739258e-10f;   // -> [-0.5, 0.5]
  float x2 = x * x;
  float p =            0.0821458866f;     // deg-9 odd poly for sin(pi x)
  p = fmaf(p, x2, -0.599264529f);
  p = fmaf(p, x2,  2.55016404f);
  p = fmaf(p, x2, -5.16771278f);
  p = fmaf(p, x2,  3.14159265f);
  return (x * 0.1f) * p;
}

// ---------------- K1: per-chunk u64 sums ----------------
__global__ void __launch_bounds__(TPB) k_chunksum(const float* __restrict__ f0, RandIniFx ri) {
  int b = blockIdx.y, c = blockIdx.x;
  int base = c * CHUNK;
  int n = min(CHUNK, Tn - base);
  int tid = threadIdx.x;

  unsigned long long acc[DIMn];
#pragma unroll
  for (int h = 0; h < DIMn; h++) acc[h] = 0ull;

  int s0 = tid * SPT;
  if (s0 < n) {
    const float4* p = reinterpret_cast<const float4*>(f0 + (size_t)b * Tn + base + s0);
    float4 a = p[0], bb = p[1];
    float fv[8] = {a.x, a.y, a.z, a.w, bb.x, bb.y, bb.z, bb.w};
#pragma unroll
    for (int j = 0; j < 8; j++) {
      bool first = (base + s0 + j) == 0;
#pragma unroll
      for (int h = 0; h < DIMn; h++) {
        unsigned long long r = (unsigned long long)rad_fx(fv[j], h);
        if (first) r += ri.v[b * DIMn + h];
        acc[h] += r;
      }
    }
  }

#pragma unroll
  for (int h = 0; h < DIMn; h++) {
    unsigned long long x = acc[h];
#pragma unroll
    for (int o = 16; o > 0; o >>= 1) x += __shfl_down_sync(0xffffffffu, x, o);
    acc[h] = x;
  }
  __shared__ unsigned long long sm[TPB / 32][DIMn];
  int warp = tid >> 5, lane = tid & 31;
  if (lane == 0)
#pragma unroll
    for (int h = 0; h < DIMn; h++) sm[warp][h] = acc[h];
  __syncthreads();
  if (tid == 0) {
#pragma unroll
    for (int h = 0; h < DIMn; h++)
      g_csum[(b * DIMn + h) * NCH + c] = sm[0][h] + sm[1][h] + sm[2][h] + sm[3][h];
  }
}

// ---------------- K2: exclusive scan of chunk sums ----------------
__global__ void k_scan() {
  int s = blockIdx.x;
  int lane = threadIdx.x;
  constexpr int PER = (NCH + 31) / 32;   // 15
  unsigned long long* row = &g_csum[(size_t)s * NCH];

  unsigned long long v[PER];
  unsigned long long tot = 0ull;
  int st = lane * PER;
#pragma unroll
  for (int j = 0; j < PER; j++) {
    int c = st + j;
    v[j] = (c < NCH) ? row[c] : 0ull;
    tot += v[j];
  }
  unsigned long long x = tot;
#pragma unroll
  for (int o = 1; o < 32; o <<= 1) {
    unsigned long long y = __shfl_up_sync(0xffffffffu, x, o);
    if (lane >= o) x += y;
  }
  unsigned long long run = x - tot;
#pragma unroll
  for (int j = 0; j < PER; j++) {
    int c = st + j;
    if (c < NCH) {
      unsigned long long old = v[j];
      row[c] = run;
      run += old;
    }
  }
}

// ---------------- K3: main (no rfx cache — recompute rads; low reg pressure)
__global__ void __launch_bounds__(TPB) k_main(const float* __restrict__ f0,
                                              float* __restrict__ out,
                                              RandIniFx ri, NKey nk) {
  int b = blockIdx.y, c = blockIdx.x;
  int base = c * CHUNK;
  int n = min(CHUNK, Tn - base);
  int tid = threadIdx.x;
  int warp = tid >> 5, lane = tid & 31;
  int s0 = tid * SPT;
  bool act = s0 < n;

  __shared__ float so[TPB * 73];      // pad 73: conflict-free STS and sweep LDS
  __shared__ unsigned long long wsum[TPB / 32][DIMn];

  float fv[8];
  if (act) {
    const float4* p = reinterpret_cast<const float4*>(f0 + (size_t)b * Tn + base + s0);
    float4 a = p[0], bb = p[1];
    fv[0]=a.x; fv[1]=a.y; fv[2]=a.z; fv[3]=a.w;
    fv[4]=bb.x; fv[5]=bb.y; fv[6]=bb.z; fv[7]=bb.w;
  }

  // pass 1: thread-local u64 sums over 8 samples (rads recomputed later)
  unsigned long long run[DIMn];   // will become running phase; reused as acc
#pragma unroll
  for (int h = 0; h < DIMn; h++) run[h] = 0ull;
  if (act) {
#pragma unroll
    for (int j = 0; j < 8; j++) {
      bool first = (base + s0 + j) == 0;
#pragma unroll
      for (int h = 0; h < DIMn; h++) {
        unsigned long long rr = (unsigned long long)rad_fx(fv[j], h);
        if (first) rr += ri.v[b * DIMn + h];
        run[h] += rr;
      }
    }
  }

  // warp-inclusive scan per harmonic; convert run -> thread-exclusive start
#pragma unroll
  for (int h = 0; h < DIMn; h++) {
    unsigned long long acch = run[h];
    unsigned long long x = acch;
#pragma unroll
    for (int o = 1; o < 32; o <<= 1) {
      unsigned long long y = __shfl_up_sync(0xffffffffu, x, o);
      if (lane >= o) x += y;
    }
    if (lane == 31) wsum[warp][h] = x;
    run[h] = x - acch;                 // warp-exclusive prefix
  }
  __syncthreads();

#pragma unroll
  for (int h = 0; h < DIMn; h++) {
    unsigned long long wex = 0ull;
#pragma unroll
    for (int w = 0; w < TPB / 32; w++)
      if (w < warp) wex += wsum[w][h];
    run[h] += g_csum[(b * DIMn + h) * NCH + c] + wex;
  }

  if (act) {
#pragma unroll
    for (int j = 0; j < 8; j++) {
      float v = fv[j];
      int t = base + s0 + j;
      uint32_t idxbase = ((uint32_t)(b * Tn + t)) * (uint32_t)DIMn;
      float uv  = (v > 0.0f) ? 1.0f : 0.0f;
      float amp = uv * 0.003f + (1.0f - uv) * (0.1f / 3.0f);
      int slot = tid * 73 + j * DIMn;
#pragma unroll
      for (int h = 0; h < DIMn; h++) {
        unsigned long long rr = (unsigned long long)rad_fx(v, h);
        if (t == 0) rr += ri.v[b * DIMn + h];
        run[h] += rr;
        uint32_t p32 = (uint32_t)(run[h] >> 1);     // frac bits [32:1]
        float sw = sine_from_p32(p32);              // sin(2*pi*frac)*0.1

        uint32_t bits = rng_bits(nk.k0, nk.k1, idxbase + (uint32_t)h);
        float u = fmaxf(LO_NORMAL, fmaf(bits01(bits), 2.0f, LO_NORMAL));
        float nr = SQRT2F * erfinv_xla(u);

        so[slot + h] = sw * uv + amp * nr;
      }
    }
  }

  __syncthreads();
  int words = n * DIMn;
  size_t outbase = ((size_t)b * Tn + (size_t)base) * (size_t)DIMn;
  for (int w = tid; w < words; w += TPB) {
    int th = w / 72;
    int of = w - th * 72;
    out[outbase + (size_t)w] = so[th * 73 + of];
  }
}

// ---------------- host ----------------
extern "C" void kernel_launch(void* const* d_in, const int* in_sizes, int n_in,
                              void* d_out, int out_size) {
  (void)in_sizes; (void)n_in; (void)out_size;
  const float* f0 = (const float*)d_in[0];
  float* out = (float*)d_out;

  uint32_t ik0, ik1, nk0, nk1;
  { uint32_t a, b;
    tf2x32(0u, 42u, 0u, 0u, a, b); ik0 = a; ik1 = b;
    tf2x32(0u, 42u, 0u, 1u, a, b); nk0 = a; nk1 = b; }

  RandIniFx ri;
  for (uint32_t i = 0; i < (uint32_t)(Bn * DIMn); i++) {
    uint32_t bits = rng_bits(ik0, ik1, i);
    float u = bits01(bits);
    if (u < 0.0f) u = 0.0f;
    ri.v[i] = (unsigned long long)((double)u * 8589934592.0);  // u is mult of 2^-23
  }
  for (int b = 0; b < Bn; b++) ri.v[b * DIMn] = 0ull;

  NKey nk{nk0, nk1};

  dim3 grid(NCH, Bn);
  k_chunksum<<<grid, TPB>>>(f0, ri);
  k_scan<<<Bn * DIMn, 32>>>();
  k_main<<<grid, TPB>>>(f0, out, ri, nk);
}

// round 5
// speedup vs baseline: 3.6471x; 1.1614x over previous
#include <cuda_runtime.h>
#include <stdint.h>
#include <math.h>

constexpr int Bn   = 4;
constexpr int Tn   = 480000;
constexpr int DIMn = 9;
constexpr int CHUNK = 512;
constexpr int TPB   = 128;
constexpr int SPT   = CHUNK / TPB;               // 4
constexpr int NCH   = (Tn + CHUNK - 1) / CHUNK;  // 938

constexpr float LO_NORMAL = -0.99999994f;
constexpr float SQRT2F    = 1.41421356237309504880f;
constexpr float RCP48K    = 2.08333333333333333e-05f;  // fl(1/48000)

constexpr int WPS = SPT * DIMn;       // 36 words per thread
constexpr int WPSP = WPS + 1;         // padded stride 37

struct RandIniFx { unsigned long long v[Bn * DIMn]; };
struct NKey      { uint32_t k0, k1; };

// per-(b,h) per-chunk u64 fixed-point sums (2^-33 turns); K2 -> exclusive prefixes
__device__ unsigned long long g_csum[Bn * DIMn * NCH];

// ---------------- threefry2x32-20 ----------------
__host__ __device__ __forceinline__ uint32_t rotl32(uint32_t x, int r) {
#ifdef __CUDA_ARCH__
  return __funnelshift_l(x, x, r);
#else
  return (x << r) | (x >> (32 - r));
#endif
}

__host__ __device__ __forceinline__ void tf2x32(uint32_t k0, uint32_t k1,
                                                uint32_t x0, uint32_t x1,
                                                uint32_t& o0, uint32_t& o1) {
  uint32_t k2 = k0 ^ k1 ^ 0x1BD11BDAu;
#define TFR(r) { x0 += x1; x1 = rotl32(x1, (r)); x1 ^= x0; }
  x0 += k0; x1 += k1;
  TFR(13) TFR(15) TFR(26) TFR(6)
  x0 += k1; x1 += k2 + 1u;
  TFR(17) TFR(29) TFR(16) TFR(24)
  x0 += k2; x1 += k0 + 2u;
  TFR(13) TFR(15) TFR(26) TFR(6)
  x0 += k0; x1 += k1 + 3u;
  TFR(17) TFR(29) TFR(16) TFR(24)
  x0 += k1; x1 += k2 + 4u;
  TFR(13) TFR(15) TFR(26) TFR(6)
  x0 += k2; x1 += k0 + 5u;
#undef TFR
  o0 = x0; o1 = x1;
}

__host__ __device__ __forceinline__ uint32_t rng_bits(uint32_t k0, uint32_t k1,
                                                      uint32_t idx) {
  uint32_t a, b;
  tf2x32(k0, k1, 0u, idx, a, b);
  return a ^ b;
}

__host__ __device__ __forceinline__ float bits01(uint32_t bits) {
  union { uint32_t u; float f; } c;
  c.u = (bits >> 9) | 0x3F800000u;
  return c.f - 1.0f;
}

// ---------------- XLA ErfInv32 (fast log; noise error budget ~1e-2) --------
__device__ __forceinline__ float erfinv_xla(float x) {
  float w = -__logf(fmaf(-x, x, 1.0f));
  float p;
  if (w < 5.0f) {
    w = w - 2.5f;
    p =             2.81022636e-08f;
    p = fmaf(p, w,  3.43273939e-07f);
    p = fmaf(p, w, -3.5233877e-06f);
    p = fmaf(p, w, -4.39150654e-06f);
    p = fmaf(p, w,  0.00021858087f);
    p = fmaf(p, w, -0.00125372503f);
    p = fmaf(p, w, -0.00417768164f);
    p = fmaf(p, w,  0.246640727f);
    p = fmaf(p, w,  1.50140941f);
  } else {
    w = sqrtf(w) - 3.0f;
    p =            -0.000200214257f;
    p = fmaf(p, w,  0.000100950558f);
    p = fmaf(p, w,  0.00134934322f);
    p = fmaf(p, w, -0.00367342844f);
    p = fmaf(p, w,  0.00573950773f);
    p = fmaf(p, w, -0.0076224613f);
    p = fmaf(p, w,  0.00943887047f);
    p = fmaf(p, w,  1.00167406f);
    p = fmaf(p, w,  2.83297682f);
  }
  return p * x;
}

// correctly-rounded x/48000 via Markstein (bit-identical to __fdiv_rn)
__device__ __forceinline__ float div48k(float x) {
  float q0 = __fmul_rn(x, RCP48K);
  float e  = fmaf(-48000.0f, q0, x);
  return fmaf(e, RCP48K, q0);
}

// rad in u32 fixed point (2^-33 turns) — exact
__device__ __forceinline__ uint32_t rad_fx(float f0v, int h) {
  float rad = div48k(__fmul_rn(f0v, (float)(h + 1)));
  return (uint32_t)(rad * 8589934592.0f);   // rad * 2^33
}

// sin(2*pi*frac) * 0.1 from u32 phase (2^-32 turns). No MUFU.
__device__ __forceinline__ float sine_from_p32(uint32_t p32) {
  bool refl = (int32_t)(p32 + 0x40000000u) < 0;
  int32_t yi = refl ? (int32_t)(0x80000000u - p32) : (int32_t)p32;
  float x  = (float)yi * 4.65661287307739258e-10f;   // -> [-0.5, 0.5]
  float x2 = x * x;
  float p =            0.0821458866f;     // deg-9 odd poly for sin(pi x)
  p = fmaf(p, x2, -0.599264529f);
  p = fmaf(p, x2,  2.55016404f);
  p = fmaf(p, x2, -5.16771278f);
  p = fmaf(p, x2,  3.14159265f);
  return (x * 0.1f) * p;
}

// ---------------- K1: per-chunk u64 sums ----------------
__global__ void __launch_bounds__(TPB) k_chunksum(const float* __restrict__ f0, RandIniFx ri) {
  int b = blockIdx.y, c = blockIdx.x;
  int base = c * CHUNK;
  int n = min(CHUNK, Tn - base);
  int tid = threadIdx.x;

  unsigned long long acc[DIMn];
#pragma unroll
  for (int h = 0; h < DIMn; h++) acc[h] = 0ull;

  int s0 = tid * SPT;
  if (s0 < n) {
    const float4 a = *reinterpret_cast<const float4*>(f0 + (size_t)b * Tn + base + s0);
    float fv[4] = {a.x, a.y, a.z, a.w};
#pragma unroll
    for (int j = 0; j < SPT; j++) {
      bool first = (base + s0 + j) == 0;
#pragma unroll
      for (int h = 0; h < DIMn; h++) {
        unsigned long long r = (unsigned long long)rad_fx(fv[j], h);
        if (first) r += ri.v[b * DIMn + h];
        acc[h] += r;
      }
    }
  }

#pragma unroll
  for (int h = 0; h < DIMn; h++) {
    unsigned long long x = acc[h];
#pragma unroll
    for (int o = 16; o > 0; o >>= 1) x += __shfl_down_sync(0xffffffffu, x, o);
    acc[h] = x;
  }
  __shared__ unsigned long long sm[TPB / 32][DIMn];
  int warp = tid >> 5, lane = tid & 31;
  if (lane == 0)
#pragma unroll
    for (int h = 0; h < DIMn; h++) sm[warp][h] = acc[h];
  __syncthreads();
  if (tid == 0) {
#pragma unroll
    for (int h = 0; h < DIMn; h++)
      g_csum[(b * DIMn + h) * NCH + c] = sm[0][h] + sm[1][h] + sm[2][h] + sm[3][h];
  }
}

// ---------------- K2: exclusive scan of chunk sums ----------------
__global__ void k_scan() {
  int s = blockIdx.x;
  int lane = threadIdx.x;
  constexpr int PER = (NCH + 31) / 32;   // 30
  unsigned long long* row = &g_csum[(size_t)s * NCH];

  unsigned long long v[PER];
  unsigned long long tot = 0ull;
  int st = lane * PER;
#pragma unroll
  for (int j = 0; j < PER; j++) {
    int c = st + j;
    v[j] = (c < NCH) ? row[c] : 0ull;
    tot += v[j];
  }
  unsigned long long x = tot;
#pragma unroll
  for (int o = 1; o < 32; o <<= 1) {
    unsigned long long y = __shfl_up_sync(0xffffffffu, x, o);
    if (lane >= o) x += y;
  }
  unsigned long long run = x - tot;
#pragma unroll
  for (int j = 0; j < PER; j++) {
    int c = st + j;
    if (c < NCH) {
      unsigned long long old = v[j];
      row[c] = run;
      run += old;
    }
  }
}

// ---------------- K3: main (SPT=4, 18.9KB staging -> higher occupancy) -----
__global__ void __launch_bounds__(TPB) k_main(const float* __restrict__ f0,
                                              float* __restrict__ out,
                                              RandIniFx ri, NKey nk) {
  int b = blockIdx.y, c = blockIdx.x;
  int base = c * CHUNK;
  int n = min(CHUNK, Tn - base);
  int tid = threadIdx.x;
  int warp = tid >> 5, lane = tid & 31;
  int s0 = tid * SPT;
  bool act = s0 < n;

  __shared__ float so[TPB * WPSP];    // 128*37 floats = 18.9KB, conflict-free
  __shared__ unsigned long long wsum[TPB / 32][DIMn];

  float fv[SPT];
  if (act) {
    const float4 a = *reinterpret_cast<const float4*>(f0 + (size_t)b * Tn + base + s0);
    fv[0]=a.x; fv[1]=a.y; fv[2]=a.z; fv[3]=a.w;
  }

  // pass 1: thread-local u64 sums (rads recomputed in emit)
  unsigned long long run[DIMn];
#pragma unroll
  for (int h = 0; h < DIMn; h++) run[h] = 0ull;
  if (act) {
#pragma unroll
    for (int j = 0; j < SPT; j++) {
      bool first = (base + s0 + j) == 0;
#pragma unroll
      for (int h = 0; h < DIMn; h++) {
        unsigned long long rr = (unsigned long long)rad_fx(fv[j], h);
        if (first) rr += ri.v[b * DIMn + h];
        run[h] += rr;
      }
    }
  }

  // warp-inclusive scan per harmonic; run -> thread-exclusive start
#pragma unroll
  for (int h = 0; h < DIMn; h++) {
    unsigned long long acch = run[h];
    unsigned long long x = acch;
#pragma unroll
    for (int o = 1; o < 32; o <<= 1) {
      unsigned long long y = __shfl_up_sync(0xffffffffu, x, o);
      if (lane >= o) x += y;
    }
    if (lane == 31) wsum[warp][h] = x;
    run[h] = x - acch;
  }
  __syncthreads();

#pragma unroll
  for (int h = 0; h < DIMn; h++) {
    unsigned long long wex = 0ull;
#pragma unroll
    for (int w = 0; w < TPB / 32; w++)
      if (w < warp) wex += wsum[w][h];
    run[h] += g_csum[(b * DIMn + h) * NCH + c] + wex;
  }

  if (act) {
#pragma unroll
    for (int j = 0; j < SPT; j++) {
      float v = fv[j];
      int t = base + s0 + j;
      uint32_t idxbase = ((uint32_t)(b * Tn + t)) * (uint32_t)DIMn;
      float uv  = (v > 0.0f) ? 1.0f : 0.0f;
      float amp = uv * 0.003f + (1.0f - uv) * (0.1f / 3.0f);
      int slot = tid * WPSP + j * DIMn;
#pragma unroll
      for (int h = 0; h < DIMn; h++) {
        unsigned long long rr = (unsigned long long)rad_fx(v, h);
        if (t == 0) rr += ri.v[b * DIMn + h];
        run[h] += rr;
        uint32_t p32 = (uint32_t)(run[h] >> 1);
        float sw = sine_from_p32(p32);

        uint32_t bits = rng_bits(nk.k0, nk.k1, idxbase + (uint32_t)h);
        float u = fmaxf(LO_NORMAL, fmaf(bits01(bits), 2.0f, LO_NORMAL));
        float nr = SQRT2F * erfinv_xla(u);

        so[slot + h] = sw * uv + amp * nr;
      }
    }
  }

  __syncthreads();
  int words = n * DIMn;
  size_t outbase = ((size_t)b * Tn + (size_t)base) * (size_t)DIMn;
  for (int w = tid; w < words; w += TPB) {
    int th = w / WPS;
    int of = w - th * WPS;
    out[outbase + (size_t)w] = so[th * WPSP + of];
  }
}

// ---------------- host ----------------
extern "C" void kernel_launch(void* const* d_in, const int* in_sizes, int n_in,
                              void* d_out, int out_size) {
  (void)in_sizes; (void)n_in; (void)out_size;
  const float* f0 = (const float*)d_in[0];
  float* out = (float*)d_out;

  uint32_t ik0, ik1, nk0, nk1;
  { uint32_t a, b;
    tf2x32(0u, 42u, 0u, 0u, a, b); ik0 = a; ik1 = b;
    tf2x32(0u, 42u, 0u, 1u, a, b); nk0 = a; nk1 = b; }

  RandIniFx ri;
  for (uint32_t i = 0; i < (uint32_t)(Bn * DIMn); i++) {
    uint32_t bits = rng_bits(ik0, ik1, i);
    float u = bits01(bits);
    if (u < 0.0f) u = 0.0f;
    ri.v[i] = (unsigned long long)((double)u * 8589934592.0);
  }
  for (int b = 0; b < Bn; b++) ri.v[b * DIMn] = 0ull;

  NKey nk{nk0, nk1};

  dim3 grid(NCH, Bn);
  k_chunksum<<<grid, TPB>>>(f0, ri);
  k_scan<<<Bn * DIMn, 32>>>();
  k_main<<<grid, TPB>>>(f0, out, ri, nk);
}